// round 1
// baseline (speedup 1.0000x reference)
#include <cuda_runtime.h>
#include <math.h>

#define NN 10000
#define EE 320000
#define ET (EE + NN)
#define FIN 128
#define HC 256
#define NH1 16
#define NC1 16
#define GG 64
#define LL 10

// ---------------- scratch (device globals; no allocation allowed) ----------
__device__ float g_h1[NN * HC];      // layer1 pre-attn features  h = x@W1
__device__ float g_out1[NN * HC];    // layer1 aggregated output
__device__ float g_h2[NN * HC];      // layer2 pre-attn features
__device__ float g_out2[NN * HC];    // layer2 aggregated output
__device__ float g_als1[NN * NH1];
__device__ float g_ald1[NN * NH1];
__device__ float g_m1[NN * NH1];
__device__ float g_s1[NN * NH1];
__device__ float g_als2[NN];
__device__ float g_ald2[NN];
__device__ float g_m2[NN];
__device__ float g_s2[NN];
__device__ float g_sums[GG * HC];
__device__ float g_cnts[GG];

// ---------------- helpers ---------------------------------------------------
__device__ __forceinline__ void atomicMaxF(float* addr, float v) {
    // monotonic trick: signed-int max for v>=0, unsigned min for v<0.
    if (v >= 0.f)
        atomicMax((int*)addr, __float_as_int(v));
    else
        atomicMin((unsigned int*)addr, __float_as_uint(v));
}

__device__ __forceinline__ void redAdd4(float4* addr, float4 v) {
    asm volatile("red.global.add.v4.f32 [%0], {%1, %2, %3, %4};"
                 :: "l"(addr), "f"(v.x), "f"(v.y), "f"(v.z), "f"(v.w)
                 : "memory");
}

__device__ __forceinline__ float leaky(float v) {
    return v >= 0.f ? v : 0.2f * v;
}

// ---------------- init ------------------------------------------------------
__global__ void init_all() {
    int i0 = blockIdx.x * blockDim.x + threadIdx.x;
    int st = gridDim.x * blockDim.x;
    for (int i = i0; i < NN * HC; i += st) { g_out1[i] = 0.f; g_out2[i] = 0.f; }
    for (int i = i0; i < NN * NH1; i += st) { g_s1[i] = 0.f; g_m1[i] = -INFINITY; }
    for (int i = i0; i < NN; i += st)       { g_s2[i] = 0.f; g_m2[i] = -INFINITY; }
    for (int i = i0; i < GG * HC; i += st)  g_sums[i] = 0.f;
    for (int i = i0; i < GG; i += st)       g_cnts[i] = 0.f;
}

// ---------------- GEMM: Hout[N,256] = X[N,K] @ W[K,256] --------------------
// LAYER==1: X = x input (K=128), out = g_h1
// LAYER==2: X = relu(g_out1 + b1) (K=256), out = g_h2
template <int LAYER>
__global__ void gemm_k(const float* __restrict__ Xin,
                       const float* __restrict__ W,
                       const float* __restrict__ bin) {
    constexpr int K = (LAYER == 1) ? FIN : HC;
    const float* __restrict__ X = (LAYER == 1) ? Xin : g_out1;
    float* __restrict__ Hout = (LAYER == 1) ? g_h1 : g_h2;

    __shared__ float xs[16][K];
    int row0 = blockIdx.x * 16;
    int col = threadIdx.x;

    for (int i = threadIdx.x; i < 16 * K; i += 256) {
        int r = i / K, k = i - r * K;
        float v = X[(size_t)(row0 + r) * K + k];
        if (LAYER == 2) v = fmaxf(v + bin[k], 0.f);
        xs[r][k] = v;
    }
    __syncthreads();

    float acc[16];
#pragma unroll
    for (int r = 0; r < 16; r++) acc[r] = 0.f;

#pragma unroll 4
    for (int k = 0; k < K; k++) {
        float w = W[k * HC + col];
#pragma unroll
        for (int r = 0; r < 16; r++) acc[r] = fmaf(xs[r][k], w, acc[r]);
    }
#pragma unroll
    for (int r = 0; r < 16; r++)
        Hout[(size_t)(row0 + r) * HC + col] = acc[r];
}

// ---------------- attention logits: al_s/al_d per (node, head) -------------
template <int H, int CH>
__global__ void attn_k(const float* __restrict__ a_src,
                       const float* __restrict__ a_dst) {
    const float* __restrict__ h = (H == NH1) ? g_h1 : g_h2;
    float* als = (H == NH1) ? g_als1 : g_als2;
    float* ald = (H == NH1) ? g_ald1 : g_ald2;

    int idx = blockIdx.x * blockDim.x + threadIdx.x;
    if (idx >= NN * H) return;
    int node = idx / H, hd = idx - node * H;
    const float* hp = h + (size_t)node * HC + hd * CH;
    float s1 = 0.f, s2 = 0.f;
#pragma unroll 8
    for (int c = 0; c < CH; c++) {
        float v = hp[c];
        s1 = fmaf(v, a_src[hd * CH + c], s1);
        s2 = fmaf(v, a_dst[hd * CH + c], s2);
    }
    als[idx] = s1;
    ald[idx] = s2;
}

// ---------------- edge pass 1: segment max ----------------------------------
template <int H>
__global__ void edge_max_k(const int* __restrict__ src, const int* __restrict__ dst) {
    const float* als = (H == NH1) ? g_als1 : g_als2;
    const float* ald = (H == NH1) ? g_ald1 : g_ald2;
    float* m = (H == NH1) ? g_m1 : g_m2;

    int i = blockIdx.x * blockDim.x + threadIdx.x;
    if (i >= ET * H) return;
    int e = i / H, hd = i - e * H;
    int s, d;
    if (e < EE) { s = src[e]; d = dst[e]; }
    else        { s = d = e - EE; }
    float v = leaky(als[s * H + hd] + ald[d * H + hd]);
    atomicMaxF(&m[d * H + hd], v);
}

// ---------------- edge pass 2: exp-sum ---------------------------------------
template <int H>
__global__ void edge_expsum_k(const int* __restrict__ src, const int* __restrict__ dst) {
    const float* als = (H == NH1) ? g_als1 : g_als2;
    const float* ald = (H == NH1) ? g_ald1 : g_ald2;
    const float* m = (H == NH1) ? g_m1 : g_m2;
    float* sden = (H == NH1) ? g_s1 : g_s2;

    int i = blockIdx.x * blockDim.x + threadIdx.x;
    if (i >= ET * H) return;
    int e = i / H, hd = i - e * H;
    int s, d;
    if (e < EE) { s = src[e]; d = dst[e]; }
    else        { s = d = e - EE; }
    float v = leaky(als[s * H + hd] + ald[d * H + hd]);
    float ex = __expf(v - m[d * H + hd]);
    atomicAdd(&sden[d * H + hd], ex);
}

// ---------------- edge pass 3: weighted scatter-add (warp per edge) ---------
template <int H>
__global__ void edge_scatter_k(const int* __restrict__ src, const int* __restrict__ dst) {
    const float* __restrict__ h = (H == NH1) ? g_h1 : g_h2;
    const float* als = (H == NH1) ? g_als1 : g_als2;
    const float* ald = (H == NH1) ? g_ald1 : g_ald2;
    const float* m = (H == NH1) ? g_m1 : g_m2;
    const float* sden = (H == NH1) ? g_s1 : g_s2;
    float* out = (H == NH1) ? g_out1 : g_out2;

    int w = (blockIdx.x * blockDim.x + threadIdx.x) >> 5;
    int lane = threadIdx.x & 31;
    if (w >= ET) return;
    int s, d;
    if (w < EE) { s = src[w]; d = dst[w]; }
    else        { s = d = w - EE; }

    const float4* hs = (const float4*)(h + (size_t)s * HC);
    float4* od = (float4*)(out + (size_t)d * HC);

    float a0, a1;
    if (H == NH1) {
        int h0 = lane >> 2;       // float4 j covers channels 4j..4j+3; head = j>>2
        int h1 = h0 + 8;
        float v0 = leaky(als[s * NH1 + h0] + ald[d * NH1 + h0]);
        float v1 = leaky(als[s * NH1 + h1] + ald[d * NH1 + h1]);
        a0 = __expf(v0 - m[d * NH1 + h0]) / sden[d * NH1 + h0];
        a1 = __expf(v1 - m[d * NH1 + h1]) / sden[d * NH1 + h1];
    } else {
        float v = leaky(als[s] + ald[d]);
        a0 = __expf(v - m[d]) / sden[d];
        a1 = a0;
    }

    float4 v = hs[lane];
    v.x *= a0; v.y *= a0; v.z *= a0; v.w *= a0;
    redAdd4(od + lane, v);

    v = hs[lane + 32];
    v.x *= a1; v.y *= a1; v.z *= a1; v.w *= a1;
    redAdd4(od + lane + 32, v);
}

// ---------------- pooling: segment mean accumulation ------------------------
__global__ void pool_k(const int* __restrict__ batch) {
    int i = blockIdx.x * blockDim.x + threadIdx.x;
    if (i >= NN * (HC / 4)) return;
    int node = i >> 6, j = i & 63;
    int g = batch[node];
    float4 v = ((const float4*)(g_out2 + (size_t)node * HC))[j];
    redAdd4(&((float4*)(g_sums + g * HC))[j], v);
    if (j == 0) atomicAdd(&g_cnts[g], 1.f);
}

// ---------------- final: (mean + b2) @ lin_w + lin_b ------------------------
__global__ void final_k(const float* __restrict__ b2,
                        const float* __restrict__ lw,
                        const float* __restrict__ lb,
                        float* __restrict__ out) {
    __shared__ float p[HC];
    int g = blockIdx.x;
    float cnt = fmaxf(g_cnts[g], 1.f);
    p[threadIdx.x] = g_sums[g * HC + threadIdx.x] / cnt + b2[threadIdx.x];
    __syncthreads();
    if (threadIdx.x < LL) {
        float acc = lb[threadIdx.x];
#pragma unroll 8
        for (int d = 0; d < HC; d++)
            acc = fmaf(p[d], lw[d * LL + threadIdx.x], acc);
        out[g * LL + threadIdx.x] = acc;
    }
}

// ---------------- launch -----------------------------------------------------
extern "C" void kernel_launch(void* const* d_in, const int* in_sizes, int n_in,
                              void* d_out, int out_size) {
    const float* x      = (const float*)d_in[0];
    const int*   ei     = (const int*)d_in[1];
    const int*   batch  = (const int*)d_in[2];
    const float* W1     = (const float*)d_in[3];
    const float* a_src1 = (const float*)d_in[4];
    const float* a_dst1 = (const float*)d_in[5];
    const float* b1     = (const float*)d_in[6];
    const float* W2     = (const float*)d_in[7];
    const float* a_src2 = (const float*)d_in[8];
    const float* a_dst2 = (const float*)d_in[9];
    const float* b2     = (const float*)d_in[10];
    const float* lin_w  = (const float*)d_in[11];
    const float* lin_b  = (const float*)d_in[12];
    float* out = (float*)d_out;

    const int* src = ei;
    const int* dst = ei + EE;

    init_all<<<1024, 256>>>();

    // ---- layer 1 ----
    gemm_k<1><<<NN / 16, 256>>>(x, W1, nullptr);
    attn_k<NH1, NC1><<<(NN * NH1 + 255) / 256, 256>>>(a_src1, a_dst1);
    edge_max_k<NH1><<<((long)ET * NH1 + 255) / 256, 256>>>(src, dst);
    edge_expsum_k<NH1><<<((long)ET * NH1 + 255) / 256, 256>>>(src, dst);
    edge_scatter_k<NH1><<<(ET * 32 + 255) / 256, 256>>>(src, dst);

    // ---- layer 2 (relu(out1+b1) folded into GEMM2 load) ----
    gemm_k<2><<<NN / 16, 256>>>(nullptr, W2, b1);
    attn_k<1, HC><<<(NN + 255) / 256, 256>>>(a_src2, a_dst2);
    edge_max_k<1><<<(ET + 255) / 256, 256>>>(src, dst);
    edge_expsum_k<1><<<(ET + 255) / 256, 256>>>(src, dst);
    edge_scatter_k<1><<<(ET * 32 + 255) / 256, 256>>>(src, dst);

    // ---- pool + classifier ----
    pool_k<<<(NN * (HC / 4) + 255) / 256, 256>>>(batch);
    final_k<<<GG, 256>>>(b2, lin_w, lin_b, out);
}

// round 2
// speedup vs baseline: 1.2550x; 1.2550x over previous
#include <cuda_runtime.h>
#include <math.h>

#define NN 10000
#define EE 320000
#define FIN 128
#define HC 256
#define NH1 16
#define NC1 16
#define GG 64
#define LL 10

typedef unsigned long long u64;

// ---------------- scratch ----------------------------------------------------
__device__ float g_h1[NN * HC];      // layer1 features h = x@W1
__device__ float g_out1[NN * HC];    // layer1 aggregated output (fully written)
__device__ float g_h2[NN * HC];      // layer2 features
__device__ float g_als1[NN * NH1];
__device__ float g_ald1[NN * NH1];
__device__ float g_als2[NN];
__device__ float g_ald2[NN];
__device__ float g_sums[GG * HC];
__device__ float g_cnts[GG];
__device__ int   g_rowptr[NN + 1];
__device__ int   g_deg[NN];          // histogram, then cursor
__device__ int   g_csr_src[EE];

__device__ __forceinline__ float leaky(float v) { return v >= 0.f ? v : 0.2f * v; }

__device__ __forceinline__ void redAdd4(float4* addr, float4 v) {
    asm volatile("red.global.add.v4.f32 [%0], {%1, %2, %3, %4};"
                 :: "l"(addr), "f"(v.x), "f"(v.y), "f"(v.z), "f"(v.w) : "memory");
}

__device__ __forceinline__ u64 packdup(float w) {
    u64 r; asm("mov.b64 %0, {%1, %1};" : "=l"(r) : "f"(w)); return r;
}
__device__ __forceinline__ void fma2(u64& acc, u64 x, u64 w) {
    asm("fma.rn.f32x2 %0, %1, %2, %0;" : "+l"(acc) : "l"(x), "l"(w));
}

// ---------------- init (tiny) -------------------------------------------------
__global__ void init_k() {
    int i = blockIdx.x * blockDim.x + threadIdx.x;
    if (i < NN) g_deg[i] = 0;
    if (i < GG * HC) g_sums[i] = 0.f;
    if (i < GG) g_cnts[i] = 0.f;
}

// ---------------- CSR build ---------------------------------------------------
__global__ void csr_count(const int* __restrict__ dst) {
    int i = blockIdx.x * blockDim.x + threadIdx.x;
    if (i < EE) atomicAdd(&g_deg[dst[i]], 1);
}

__global__ void csr_scan() {
    __shared__ int part[256];
    const int CH = 40;                      // 256*40 >= NN
    int t = threadIdx.x;
    int base = t * CH;
    int s = 0;
    for (int j = 0; j < CH; j++) { int idx = base + j; if (idx < NN) s += g_deg[idx]; }
    part[t] = s;
    __syncthreads();
    for (int o = 1; o < 256; o <<= 1) {
        int v = (t >= o) ? part[t - o] : 0;
        __syncthreads();
        part[t] += v;
        __syncthreads();
    }
    int run = (t == 0) ? 0 : part[t - 1];
    for (int j = 0; j < CH; j++) {
        int idx = base + j;
        if (idx < NN) {
            g_rowptr[idx] = run;
            run += g_deg[idx];
            g_deg[idx] = 0;                 // reset for cursor use
            if (idx == NN - 1) g_rowptr[NN] = run;
        }
    }
}

__global__ void csr_fill(const int* __restrict__ src, const int* __restrict__ dst) {
    int i = blockIdx.x * blockDim.x + threadIdx.x;
    if (i >= EE) return;
    int d = dst[i];
    int p = atomicAdd(&g_deg[d], 1);
    g_csr_src[g_rowptr[d] + p] = src[i];
}

// ---------------- GEMM: Hout[N,256] = X[N,K] @ W[K,256]  (f32x2 packed) -------
// thread = 1 column x 32 rows (16 row-pairs). x tile transposed in smem.
template <int LAYER>
__global__ void gemm_k(const float* __restrict__ Xin,
                       const float* __restrict__ W,
                       const float* __restrict__ bin) {
    constexpr int K = (LAYER == 1) ? FIN : HC;
    const float* __restrict__ X = (LAYER == 1) ? Xin : g_out1;
    float* __restrict__ Hout = (LAYER == 1) ? g_h1 : g_h2;

    __shared__ u64 xst[K * 16];             // [k][row_pair]
    float* xs = (float*)xst;                // [k][row], row-pairs adjacent

    int row0 = blockIdx.x * 32;
    int col = threadIdx.x;

    for (int i = threadIdx.x; i < 32 * K; i += 256) {
        int r = i & 31, k = i >> 5;
        int row = row0 + r;
        float v = 0.f;
        if (row < NN) {
            v = X[(size_t)row * K + k];
            if (LAYER == 2) v = fmaxf(v + bin[k], 0.f);
        }
        xs[k * 32 + r] = v;
    }
    __syncthreads();

    u64 acc[16];
#pragma unroll
    for (int p = 0; p < 16; p++) acc[p] = 0ull;

#pragma unroll 4
    for (int k = 0; k < K; k++) {
        u64 wp = packdup(W[k * HC + col]);
        const u64* xp = xst + k * 16;
#pragma unroll
        for (int p = 0; p < 16; p++) fma2(acc[p], xp[p], wp);
    }

#pragma unroll
    for (int p = 0; p < 16; p++) {
        float lo, hi;
        asm("mov.b64 {%0, %1}, %2;" : "=f"(lo), "=f"(hi) : "l"(acc[p]));
        int r0 = row0 + 2 * p;
        if (r0 < NN)     Hout[(size_t)r0 * HC + col] = lo;
        if (r0 + 1 < NN) Hout[(size_t)(r0 + 1) * HC + col] = hi;
    }
}

// ---------------- attention logit vectors ------------------------------------
template <int H, int CH>
__global__ void attn_k(const float* __restrict__ a_src,
                       const float* __restrict__ a_dst) {
    const float* __restrict__ h = (H == NH1) ? g_h1 : g_h2;
    float* als = (H == NH1) ? g_als1 : g_als2;
    float* ald = (H == NH1) ? g_ald1 : g_ald2;

    int idx = blockIdx.x * blockDim.x + threadIdx.x;
    if (idx >= NN * H) return;
    int node = idx / H, hd = idx - node * H;
    const float* hp = h + (size_t)node * HC + hd * CH;
    float s1 = 0.f, s2 = 0.f;
#pragma unroll 8
    for (int c = 0; c < CH; c++) {
        float v = hp[c];
        s1 = fmaf(v, a_src[hd * CH + c], s1);
        s2 = fmaf(v, a_dst[hd * CH + c], s2);
    }
    als[idx] = s1;
    ald[idx] = s2;
}

// ---------------- fused GAT layer 1 (16 heads), warp per dst ------------------
__global__ void gat1_k() {
    int w = (blockIdx.x * blockDim.x + threadIdx.x) >> 5;
    int lane = threadIdx.x & 31;
    if (w >= NN) return;
    const int d = w;
    const int hh = lane & 15;

    float ald_h = g_ald1[d * NH1 + hh];
    float self_e = leaky(g_als1[d * NH1 + hh] + ald_h);
    int beg = g_rowptr[d], end = g_rowptr[d + 1];

    // pass 1: per-head max over incoming edges + self (2 edges per step)
    float m = self_e;
    for (int i = beg + (lane >> 4); i < end; i += 2) {
        int s = g_csr_src[i];
        m = fmaxf(m, leaky(g_als1[s * NH1 + hh] + ald_h));
    }
    m = fmaxf(m, __shfl_xor_sync(0xffffffffu, m, 16));

    // pass 2: unnormalized accumulate + denominator
    // lane owns float4 chunks {lane, lane+32}: heads lane>>2 and (lane>>2)+8
    int h0 = lane >> 2, h1 = h0 + 8;
    float4 acc0 = {0.f, 0.f, 0.f, 0.f}, acc1 = {0.f, 0.f, 0.f, 0.f};

    float wself = __expf(self_e - m);
    float ssum = wself;
    {
        float w0 = __shfl_sync(0xffffffffu, wself, h0);
        float w1 = __shfl_sync(0xffffffffu, wself, h1);
        const float4* hs = (const float4*)(g_h1 + (size_t)d * HC);
        float4 v0 = hs[lane], v1 = hs[lane + 32];
        acc0.x = fmaf(w0, v0.x, acc0.x); acc0.y = fmaf(w0, v0.y, acc0.y);
        acc0.z = fmaf(w0, v0.z, acc0.z); acc0.w = fmaf(w0, v0.w, acc0.w);
        acc1.x = fmaf(w1, v1.x, acc1.x); acc1.y = fmaf(w1, v1.y, acc1.y);
        acc1.z = fmaf(w1, v1.z, acc1.z); acc1.w = fmaf(w1, v1.w, acc1.w);
    }
    for (int i = beg; i < end; i++) {
        int s = g_csr_src[i];
        float we = __expf(leaky(g_als1[s * NH1 + hh] + ald_h) - m);
        ssum += we;
        float w0 = __shfl_sync(0xffffffffu, we, h0);
        float w1 = __shfl_sync(0xffffffffu, we, h1);
        const float4* hs = (const float4*)(g_h1 + (size_t)s * HC);
        float4 v0 = hs[lane], v1 = hs[lane + 32];
        acc0.x = fmaf(w0, v0.x, acc0.x); acc0.y = fmaf(w0, v0.y, acc0.y);
        acc0.z = fmaf(w0, v0.z, acc0.z); acc0.w = fmaf(w0, v0.w, acc0.w);
        acc1.x = fmaf(w1, v1.x, acc1.x); acc1.y = fmaf(w1, v1.y, acc1.y);
        acc1.z = fmaf(w1, v1.z, acc1.z); acc1.w = fmaf(w1, v1.w, acc1.w);
    }

    float s0 = __shfl_sync(0xffffffffu, ssum, h0);
    float s1 = __shfl_sync(0xffffffffu, ssum, h1);
    float r0 = 1.f / s0, r1 = 1.f / s1;
    float4* od = (float4*)(g_out1 + (size_t)d * HC);
    float4 o0 = {acc0.x * r0, acc0.y * r0, acc0.z * r0, acc0.w * r0};
    float4 o1 = {acc1.x * r1, acc1.y * r1, acc1.z * r1, acc1.w * r1};
    od[lane] = o0;
    od[lane + 32] = o1;
}

// ---------------- fused GAT layer 2 (1 head) + mean-pool red ------------------
__global__ void gat2_k(const int* __restrict__ batch) {
    int w = (blockIdx.x * blockDim.x + threadIdx.x) >> 5;
    int lane = threadIdx.x & 31;
    if (w >= NN) return;
    const int d = w;

    float ald_d = g_ald2[d];
    float self_e = leaky(g_als2[d] + ald_d);
    int beg = g_rowptr[d], end = g_rowptr[d + 1];

    float m = self_e;
    for (int i = beg + lane; i < end; i += 32)
        m = fmaxf(m, leaky(g_als2[g_csr_src[i]] + ald_d));
#pragma unroll
    for (int o = 16; o; o >>= 1) m = fmaxf(m, __shfl_xor_sync(0xffffffffu, m, o));

    float ssum = __expf(self_e - m);
    const float4* hd_ = (const float4*)(g_h2 + (size_t)d * HC);
    float4 v0 = hd_[lane], v1 = hd_[lane + 32];
    float4 acc0 = {ssum * v0.x, ssum * v0.y, ssum * v0.z, ssum * v0.w};
    float4 acc1 = {ssum * v1.x, ssum * v1.y, ssum * v1.z, ssum * v1.w};

    for (int i = beg; i < end; i++) {
        int s = g_csr_src[i];
        float we = __expf(leaky(g_als2[s] + ald_d) - m);
        ssum += we;
        const float4* hs = (const float4*)(g_h2 + (size_t)s * HC);
        v0 = hs[lane]; v1 = hs[lane + 32];
        acc0.x = fmaf(we, v0.x, acc0.x); acc0.y = fmaf(we, v0.y, acc0.y);
        acc0.z = fmaf(we, v0.z, acc0.z); acc0.w = fmaf(we, v0.w, acc0.w);
        acc1.x = fmaf(we, v1.x, acc1.x); acc1.y = fmaf(we, v1.y, acc1.y);
        acc1.z = fmaf(we, v1.z, acc1.z); acc1.w = fmaf(we, v1.w, acc1.w);
    }

    float inv = 1.f / ssum;
    int g = batch[d];
    float4 r0 = {acc0.x * inv, acc0.y * inv, acc0.z * inv, acc0.w * inv};
    float4 r1 = {acc1.x * inv, acc1.y * inv, acc1.z * inv, acc1.w * inv};
    redAdd4(&((float4*)(g_sums + g * HC))[lane], r0);
    redAdd4(&((float4*)(g_sums + g * HC))[lane + 32], r1);
    if (lane == 0) atomicAdd(&g_cnts[g], 1.f);
}

// ---------------- final: (mean + b2) @ lin_w + lin_b --------------------------
__global__ void final_k(const float* __restrict__ b2,
                        const float* __restrict__ lw,
                        const float* __restrict__ lb,
                        float* __restrict__ out) {
    __shared__ float p[HC];
    int g = blockIdx.x;
    float cnt = fmaxf(g_cnts[g], 1.f);
    p[threadIdx.x] = g_sums[g * HC + threadIdx.x] / cnt + b2[threadIdx.x];
    __syncthreads();
    if (threadIdx.x < LL) {
        float acc = lb[threadIdx.x];
#pragma unroll 8
        for (int d = 0; d < HC; d++)
            acc = fmaf(p[d], lw[d * LL + threadIdx.x], acc);
        out[g * LL + threadIdx.x] = acc;
    }
}

// ---------------- launch -------------------------------------------------------
extern "C" void kernel_launch(void* const* d_in, const int* in_sizes, int n_in,
                              void* d_out, int out_size) {
    const float* x      = (const float*)d_in[0];
    const int*   ei     = (const int*)d_in[1];
    const int*   batch  = (const int*)d_in[2];
    const float* W1     = (const float*)d_in[3];
    const float* a_src1 = (const float*)d_in[4];
    const float* a_dst1 = (const float*)d_in[5];
    const float* b1     = (const float*)d_in[6];
    const float* W2     = (const float*)d_in[7];
    const float* a_src2 = (const float*)d_in[8];
    const float* a_dst2 = (const float*)d_in[9];
    const float* b2     = (const float*)d_in[10];
    const float* lin_w  = (const float*)d_in[11];
    const float* lin_b  = (const float*)d_in[12];
    float* out = (float*)d_out;

    const int* src = ei;
    const int* dst = ei + EE;

    init_k<<<(GG * HC + 255) / 256, 256>>>();
    csr_count<<<(EE + 255) / 256, 256>>>(dst);
    csr_scan<<<1, 256>>>();
    csr_fill<<<(EE + 255) / 256, 256>>>(src, dst);

    // layer 1
    gemm_k<1><<<(NN + 31) / 32, 256>>>(x, W1, nullptr);
    attn_k<NH1, NC1><<<(NN * NH1 + 255) / 256, 256>>>(a_src1, a_dst1);
    gat1_k<<<(NN * 32 + 255) / 256, 256>>>();

    // layer 2 (relu(out1+b1) folded into gemm2 load)
    gemm_k<2><<<(NN + 31) / 32, 256>>>(nullptr, W2, b1);
    attn_k<1, HC><<<(NN + 255) / 256, 256>>>(a_src2, a_dst2);
    gat2_k<<<(NN * 32 + 255) / 256, 256>>>(batch);

    final_k<<<GG, 256>>>(b2, lin_w, lin_b, out);
}

// round 3
// speedup vs baseline: 1.5545x; 1.2386x over previous
#include <cuda_runtime.h>
#include <math.h>

#define NN 10000
#define EE 320000
#define FIN 128
#define HC 256
#define NH1 16
#define NC1 16
#define GG 64
#define LL 10

typedef unsigned long long u64;

// ---------------- scratch ----------------------------------------------------
__device__ float g_h1[NN * HC];      // layer1 features h = x@W1
__device__ float g_out1[NN * HC];    // layer1 aggregated output
__device__ float g_h2[NN * HC];      // layer2 features
__device__ float g_als1[NN * NH1];
__device__ float g_ald1[NN * NH1];
__device__ float g_als2[NN];
__device__ float g_ald2[NN];
__device__ float g_sums[GG * HC];
__device__ float g_cnts[GG];
__device__ int   g_rowptr[NN + 1];
__device__ int   g_deg[NN];          // histogram -> start-offset cursor
__device__ int   g_csr_src[EE];

__device__ __forceinline__ float leaky(float v) { return v >= 0.f ? v : 0.2f * v; }

__device__ __forceinline__ void redAdd4(float4* addr, float4 v) {
    asm volatile("red.global.add.v4.f32 [%0], {%1, %2, %3, %4};"
                 :: "l"(addr), "f"(v.x), "f"(v.y), "f"(v.z), "f"(v.w) : "memory");
}

__device__ __forceinline__ u64 packdup(float w) {
    u64 r; asm("mov.b64 %0, {%1, %1};" : "=l"(r) : "f"(w)); return r;
}
__device__ __forceinline__ void fma2(u64& acc, u64 x, u64 w) {
    asm("fma.rn.f32x2 %0, %1, %2, %0;" : "+l"(acc) : "l"(x), "l"(w));
}

// ---------------- init -------------------------------------------------------
__global__ void init_k() {
    int i = blockIdx.x * blockDim.x + threadIdx.x;
    if (i < NN) g_deg[i] = 0;
    if (i < GG * HC) g_sums[i] = 0.f;
    if (i < GG) g_cnts[i] = 0.f;
}

// ---------------- CSR build ---------------------------------------------------
__global__ void csr_count(const int* __restrict__ dst) {
    int i = blockIdx.x * blockDim.x + threadIdx.x;   // i indexes groups of 4
    if (i * 4 >= EE) return;
    int4 d4 = ((const int4*)dst)[i];
    atomicAdd(&g_deg[d4.x], 1);
    atomicAdd(&g_deg[d4.y], 1);
    atomicAdd(&g_deg[d4.z], 1);
    atomicAdd(&g_deg[d4.w], 1);
}

__global__ void csr_scan() {                          // 1024 threads, 1 block
    __shared__ int part[1024];
    const int CH = 10;                                // 1024*10 >= NN
    int t = threadIdx.x;
    int base = t * CH;
    int s = 0;
#pragma unroll
    for (int j = 0; j < CH; j++) { int idx = base + j; if (idx < NN) s += g_deg[idx]; }
    part[t] = s;
    __syncthreads();
    for (int o = 1; o < 1024; o <<= 1) {
        int v = (t >= o) ? part[t - o] : 0;
        __syncthreads();
        part[t] += v;
        __syncthreads();
    }
    int run = (t == 0) ? 0 : part[t - 1];
#pragma unroll
    for (int j = 0; j < CH; j++) {
        int idx = base + j;
        if (idx < NN) {
            g_rowptr[idx] = run;
            int dg = g_deg[idx];
            g_deg[idx] = run;                         // becomes write cursor
            run += dg;
            if (idx == NN - 1) g_rowptr[NN] = run;
        }
    }
}

__global__ void csr_fill(const int* __restrict__ src, const int* __restrict__ dst) {
    int i = blockIdx.x * blockDim.x + threadIdx.x;
    if (i * 4 >= EE) return;
    int4 s4 = ((const int4*)src)[i];
    int4 d4 = ((const int4*)dst)[i];
    g_csr_src[atomicAdd(&g_deg[d4.x], 1)] = s4.x;
    g_csr_src[atomicAdd(&g_deg[d4.y], 1)] = s4.y;
    g_csr_src[atomicAdd(&g_deg[d4.z], 1)] = s4.z;
    g_csr_src[atomicAdd(&g_deg[d4.w], 1)] = s4.w;
}

// ---------------- GEMM: Hout[N,256] = X[N,K] @ W[K,256]  (f32x2 packed) -------
template <int LAYER>
__global__ void gemm_k(const float* __restrict__ Xin,
                       const float* __restrict__ W,
                       const float* __restrict__ bin) {
    constexpr int K = (LAYER == 1) ? FIN : HC;
    const float* __restrict__ X = (LAYER == 1) ? Xin : g_out1;
    float* __restrict__ Hout = (LAYER == 1) ? g_h1 : g_h2;

    __shared__ u64 xst[K * 16];             // [k][row_pair]
    float* xs = (float*)xst;

    int row0 = blockIdx.x * 32;
    int col = threadIdx.x;

    for (int i = threadIdx.x; i < 32 * K; i += 256) {
        int r = i & 31, k = i >> 5;
        int row = row0 + r;
        float v = 0.f;
        if (row < NN) {
            v = X[(size_t)row * K + k];
            if (LAYER == 2) v = fmaxf(v + bin[k], 0.f);
        }
        xs[k * 32 + r] = v;
    }
    __syncthreads();

    u64 acc[16];
#pragma unroll
    for (int p = 0; p < 16; p++) acc[p] = 0ull;

#pragma unroll 4
    for (int k = 0; k < K; k++) {
        u64 wp = packdup(W[k * HC + col]);
        const u64* xp = xst + k * 16;
#pragma unroll
        for (int p = 0; p < 16; p++) fma2(acc[p], xp[p], wp);
    }

#pragma unroll
    for (int p = 0; p < 16; p++) {
        float lo, hi;
        asm("mov.b64 {%0, %1}, %2;" : "=f"(lo), "=f"(hi) : "l"(acc[p]));
        int r0 = row0 + 2 * p;
        if (r0 < NN)     Hout[(size_t)r0 * HC + col] = lo;
        if (r0 + 1 < NN) Hout[(size_t)(r0 + 1) * HC + col] = hi;
    }
}

// ---------------- attention logit vectors ------------------------------------
template <int H, int CH>
__global__ void attn_k(const float* __restrict__ a_src,
                       const float* __restrict__ a_dst) {
    const float* __restrict__ h = (H == NH1) ? g_h1 : g_h2;
    float* als = (H == NH1) ? g_als1 : g_als2;
    float* ald = (H == NH1) ? g_ald1 : g_ald2;

    int idx = blockIdx.x * blockDim.x + threadIdx.x;
    if (idx >= NN * H) return;
    int node = idx / H, hd = idx - node * H;
    const float4* hp = (const float4*)(h + (size_t)node * HC + hd * CH);
    const float4* as4 = (const float4*)(a_src + hd * CH);
    const float4* ad4 = (const float4*)(a_dst + hd * CH);
    float s1 = 0.f, s2 = 0.f;
#pragma unroll
    for (int c = 0; c < CH / 4; c++) {
        float4 v = hp[c], a = as4[c], b = ad4[c];
        s1 = fmaf(v.x, a.x, fmaf(v.y, a.y, fmaf(v.z, a.z, fmaf(v.w, a.w, s1))));
        s2 = fmaf(v.x, b.x, fmaf(v.y, b.y, fmaf(v.z, b.z, fmaf(v.w, b.w, s2))));
    }
    als[idx] = s1;
    ald[idx] = s2;
}

// ---------------- fused GAT layer 1 (16 heads), warp per dst, single pass -----
__global__ void __launch_bounds__(256) gat1_k() {
    int w = (blockIdx.x * blockDim.x + threadIdx.x) >> 5;
    int lane = threadIdx.x & 31;
    if (w >= NN) return;
    const int d = w;
    const int hh = lane & 15;
    const int h0 = lane >> 2, h1 = h0 + 8;

    float ald_h = g_ald1[d * NH1 + hh];
    float wself = __expf(leaky(g_als1[d * NH1 + hh] + ald_h));
    float ssum = wself;

    float4 acc0, acc1;
    {
        float w0 = __shfl_sync(0xffffffffu, wself, h0);
        float w1 = __shfl_sync(0xffffffffu, wself, h1);
        const float4* hs = (const float4*)(g_h1 + (size_t)d * HC);
        float4 v0 = hs[lane], v1 = hs[lane + 32];
        acc0 = make_float4(w0 * v0.x, w0 * v0.y, w0 * v0.z, w0 * v0.w);
        acc1 = make_float4(w1 * v1.x, w1 * v1.y, w1 * v1.z, w1 * v1.w);
    }

    int beg = g_rowptr[d], end = g_rowptr[d + 1];

#define GAT1_STEP(SRC)                                                          \
    {                                                                           \
        int s_ = (SRC);                                                         \
        float we = __expf(leaky(g_als1[s_ * NH1 + hh] + ald_h));                \
        ssum += we;                                                             \
        float w0 = __shfl_sync(0xffffffffu, we, h0);                            \
        float w1 = __shfl_sync(0xffffffffu, we, h1);                            \
        const float4* hs = (const float4*)(g_h1 + (size_t)s_ * HC);             \
        float4 v0 = hs[lane], v1 = hs[lane + 32];                               \
        acc0.x = fmaf(w0, v0.x, acc0.x); acc0.y = fmaf(w0, v0.y, acc0.y);       \
        acc0.z = fmaf(w0, v0.z, acc0.z); acc0.w = fmaf(w0, v0.w, acc0.w);       \
        acc1.x = fmaf(w1, v1.x, acc1.x); acc1.y = fmaf(w1, v1.y, acc1.y);       \
        acc1.z = fmaf(w1, v1.z, acc1.z); acc1.w = fmaf(w1, v1.w, acc1.w);       \
    }

    for (int base = beg; base < end; base += 32) {
        int idx = base + lane;
        int sv = (idx < end) ? g_csr_src[idx] : 0;
        int n = min(32, end - base);
        if (n == 32) {
#pragma unroll 8
            for (int j = 0; j < 32; j++) GAT1_STEP(__shfl_sync(0xffffffffu, sv, j));
        } else {
            for (int j = 0; j < n; j++) GAT1_STEP(__shfl_sync(0xffffffffu, sv, j));
        }
    }

    float s0 = __shfl_sync(0xffffffffu, ssum, h0);
    float s1 = __shfl_sync(0xffffffffu, ssum, h1);
    float r0 = 1.f / s0, r1 = 1.f / s1;
    float4* od = (float4*)(g_out1 + (size_t)d * HC);
    od[lane]      = make_float4(acc0.x * r0, acc0.y * r0, acc0.z * r0, acc0.w * r0);
    od[lane + 32] = make_float4(acc1.x * r1, acc1.y * r1, acc1.z * r1, acc1.w * r1);
}

// ---------------- fused GAT layer 2 (1 head) + mean-pool red, single pass -----
__global__ void __launch_bounds__(256) gat2_k(const int* __restrict__ batch) {
    int w = (blockIdx.x * blockDim.x + threadIdx.x) >> 5;
    int lane = threadIdx.x & 31;
    if (w >= NN) return;
    const int d = w;

    float ald_d = g_ald2[d];
    float ssum = __expf(leaky(g_als2[d] + ald_d));

    float4 acc0, acc1;
    {
        const float4* hs = (const float4*)(g_h2 + (size_t)d * HC);
        float4 v0 = hs[lane], v1 = hs[lane + 32];
        acc0 = make_float4(ssum * v0.x, ssum * v0.y, ssum * v0.z, ssum * v0.w);
        acc1 = make_float4(ssum * v1.x, ssum * v1.y, ssum * v1.z, ssum * v1.w);
    }

    int beg = g_rowptr[d], end = g_rowptr[d + 1];

#define GAT2_STEP(SRC)                                                          \
    {                                                                           \
        int s_ = (SRC);                                                         \
        float we = __expf(leaky(g_als2[s_] + ald_d));                           \
        ssum += we;                                                             \
        const float4* hs = (const float4*)(g_h2 + (size_t)s_ * HC);             \
        float4 v0 = hs[lane], v1 = hs[lane + 32];                               \
        acc0.x = fmaf(we, v0.x, acc0.x); acc0.y = fmaf(we, v0.y, acc0.y);       \
        acc0.z = fmaf(we, v0.z, acc0.z); acc0.w = fmaf(we, v0.w, acc0.w);       \
        acc1.x = fmaf(we, v1.x, acc1.x); acc1.y = fmaf(we, v1.y, acc1.y);       \
        acc1.z = fmaf(we, v1.z, acc1.z); acc1.w = fmaf(we, v1.w, acc1.w);       \
    }

    for (int base = beg; base < end; base += 32) {
        int idx = base + lane;
        int sv = (idx < end) ? g_csr_src[idx] : 0;
        int n = min(32, end - base);
        if (n == 32) {
#pragma unroll 8
            for (int j = 0; j < 32; j++) GAT2_STEP(__shfl_sync(0xffffffffu, sv, j));
        } else {
            for (int j = 0; j < n; j++) GAT2_STEP(__shfl_sync(0xffffffffu, sv, j));
        }
    }

    float inv = 1.f / ssum;
    int g = batch[d];
    float4 r0 = make_float4(acc0.x * inv, acc0.y * inv, acc0.z * inv, acc0.w * inv);
    float4 r1 = make_float4(acc1.x * inv, acc1.y * inv, acc1.z * inv, acc1.w * inv);
    redAdd4(&((float4*)(g_sums + g * HC))[lane], r0);
    redAdd4(&((float4*)(g_sums + g * HC))[lane + 32], r1);
    if (lane == 0) atomicAdd(&g_cnts[g], 1.f);
}

// ---------------- final: (mean + b2) @ lin_w + lin_b --------------------------
__global__ void final_k(const float* __restrict__ b2,
                        const float* __restrict__ lw,
                        const float* __restrict__ lb,
                        float* __restrict__ out) {
    __shared__ float p[HC];
    int g = blockIdx.x;
    float cnt = fmaxf(g_cnts[g], 1.f);
    p[threadIdx.x] = g_sums[g * HC + threadIdx.x] / cnt + b2[threadIdx.x];
    __syncthreads();
    if (threadIdx.x < LL) {
        float acc = lb[threadIdx.x];
#pragma unroll 8
        for (int d = 0; d < HC; d++)
            acc = fmaf(p[d], lw[d * LL + threadIdx.x], acc);
        out[g * LL + threadIdx.x] = acc;
    }
}

// ---------------- launch -------------------------------------------------------
extern "C" void kernel_launch(void* const* d_in, const int* in_sizes, int n_in,
                              void* d_out, int out_size) {
    const float* x      = (const float*)d_in[0];
    const int*   ei     = (const int*)d_in[1];
    const int*   batch  = (const int*)d_in[2];
    const float* W1     = (const float*)d_in[3];
    const float* a_src1 = (const float*)d_in[4];
    const float* a_dst1 = (const float*)d_in[5];
    const float* b1     = (const float*)d_in[6];
    const float* W2     = (const float*)d_in[7];
    const float* a_src2 = (const float*)d_in[8];
    const float* a_dst2 = (const float*)d_in[9];
    const float* b2     = (const float*)d_in[10];
    const float* lin_w  = (const float*)d_in[11];
    const float* lin_b  = (const float*)d_in[12];
    float* out = (float*)d_out;

    const int* src = ei;
    const int* dst = ei + EE;

    init_k<<<(GG * HC + 255) / 256, 256>>>();
    csr_count<<<(EE / 4 + 255) / 256, 256>>>(dst);
    csr_scan<<<1, 1024>>>();
    csr_fill<<<(EE / 4 + 255) / 256, 256>>>(src, dst);

    // layer 1
    gemm_k<1><<<(NN + 31) / 32, 256>>>(x, W1, nullptr);
    attn_k<NH1, NC1><<<(NN * NH1 + 255) / 256, 256>>>(a_src1, a_dst1);
    gat1_k<<<(NN * 32 + 255) / 256, 256>>>();

    // layer 2 (relu(out1+b1) folded into gemm2 load)
    gemm_k<2><<<(NN + 31) / 32, 256>>>(nullptr, W2, b1);
    attn_k<1, HC><<<(NN + 255) / 256, 256>>>(a_src2, a_dst2);
    gat2_k<<<(NN * 32 + 255) / 256, 256>>>(batch);

    final_k<<<GG, 256>>>(b2, lin_w, lin_b, out);
}

// round 4
// speedup vs baseline: 1.6536x; 1.0637x over previous
#include <cuda_runtime.h>
#include <math.h>

#define NN 10000
#define EE 320000
#define FIN 128
#define HC 256
#define NH1 16
#define NC1 16
#define GG 64
#define LL 10

typedef unsigned long long u64;

// ---------------- scratch ----------------------------------------------------
__device__ float g_h1[NN * HC];      // layer1 features h = x@W1
__device__ float g_out1[NN * HC];    // layer1 aggregated output
__device__ float g_h2[NN * HC];      // layer2 features
__device__ float g_als1[NN * NH1];
__device__ float g_ald1[NN * NH1];
__device__ float g_als2[NN];
__device__ float g_ald2[NN];
__device__ float g_sums[GG * HC];
__device__ float g_cnts[GG];
__device__ int   g_rowptr[NN + 1];
__device__ int   g_deg[NN];          // histogram -> start-offset cursor
__device__ int   g_csr_src[EE];

__device__ __forceinline__ float leaky(float v) { return v >= 0.f ? v : 0.2f * v; }

__device__ __forceinline__ void redAdd4(float4* addr, float4 v) {
    asm volatile("red.global.add.v4.f32 [%0], {%1, %2, %3, %4};"
                 :: "l"(addr), "f"(v.x), "f"(v.y), "f"(v.z), "f"(v.w) : "memory");
}

__device__ __forceinline__ u64 packdup(float w) {
    u64 r; asm("mov.b64 %0, {%1, %1};" : "=l"(r) : "f"(w)); return r;
}
__device__ __forceinline__ void fma2(u64& acc, u64 x, u64 w) {
    asm("fma.rn.f32x2 %0, %1, %2, %0;" : "+l"(acc) : "l"(x), "l"(w));
}
__device__ __forceinline__ u64 mul2(u64 x, u64 w) {
    u64 r; asm("mul.rn.f32x2 %0, %1, %2;" : "=l"(r) : "l"(x), "l"(w)); return r;
}
__device__ __forceinline__ float2 unpack2(u64 v) {
    float lo, hi; asm("mov.b64 {%0, %1}, %2;" : "=f"(lo), "=f"(hi) : "l"(v));
    return make_float2(lo, hi);
}

// ---------------- init -------------------------------------------------------
__global__ void init_k() {
    int i = blockIdx.x * blockDim.x + threadIdx.x;
    if (i < NN) g_deg[i] = 0;
    if (i < GG * HC) g_sums[i] = 0.f;
    if (i < GG) g_cnts[i] = 0.f;
}

// ---------------- CSR build ---------------------------------------------------
__global__ void csr_count(const int* __restrict__ dst) {
    int i = blockIdx.x * blockDim.x + threadIdx.x;   // groups of 4
    if (i * 4 >= EE) return;
    int4 d4 = ((const int4*)dst)[i];
    atomicAdd(&g_deg[d4.x], 1);
    atomicAdd(&g_deg[d4.y], 1);
    atomicAdd(&g_deg[d4.z], 1);
    atomicAdd(&g_deg[d4.w], 1);
}

__global__ void csr_scan() {                          // 1024 threads, 1 block
    __shared__ int part[1024];
    const int CH = 10;                                // 1024*10 >= NN
    int t = threadIdx.x;
    int base = t * CH;
    int s = 0;
#pragma unroll
    for (int j = 0; j < CH; j++) { int idx = base + j; if (idx < NN) s += g_deg[idx]; }
    part[t] = s;
    __syncthreads();
    for (int o = 1; o < 1024; o <<= 1) {
        int v = (t >= o) ? part[t - o] : 0;
        __syncthreads();
        part[t] += v;
        __syncthreads();
    }
    int run = (t == 0) ? 0 : part[t - 1];
#pragma unroll
    for (int j = 0; j < CH; j++) {
        int idx = base + j;
        if (idx < NN) {
            g_rowptr[idx] = run;
            int dg = g_deg[idx];
            g_deg[idx] = run;                         // becomes write cursor
            run += dg;
            if (idx == NN - 1) g_rowptr[NN] = run;
        }
    }
}

__global__ void csr_fill(const int* __restrict__ src, const int* __restrict__ dst) {
    int i = blockIdx.x * blockDim.x + threadIdx.x;
    if (i * 4 >= EE) return;
    int4 s4 = ((const int4*)src)[i];
    int4 d4 = ((const int4*)dst)[i];
    g_csr_src[atomicAdd(&g_deg[d4.x], 1)] = s4.x;
    g_csr_src[atomicAdd(&g_deg[d4.y], 1)] = s4.y;
    g_csr_src[atomicAdd(&g_deg[d4.z], 1)] = s4.z;
    g_csr_src[atomicAdd(&g_deg[d4.w], 1)] = s4.w;
}

// ---------------- GEMM: Hout[N,256] = X[N,K] @ W[K,256]  (f32x2 packed) -------
template <int LAYER>
__global__ void gemm_k(const float* __restrict__ Xin,
                       const float* __restrict__ W,
                       const float* __restrict__ bin) {
    constexpr int K = (LAYER == 1) ? FIN : HC;
    const float* __restrict__ X = (LAYER == 1) ? Xin : g_out1;
    float* __restrict__ Hout = (LAYER == 1) ? g_h1 : g_h2;

    __shared__ u64 xst[K * 16];             // [k][row_pair]
    float* xs = (float*)xst;

    int row0 = blockIdx.x * 32;
    int col = threadIdx.x;

    for (int i = threadIdx.x; i < 32 * K; i += 256) {
        int r = i & 31, k = i >> 5;
        int row = row0 + r;
        float v = 0.f;
        if (row < NN) {
            v = X[(size_t)row * K + k];
            if (LAYER == 2) v = fmaxf(v + bin[k], 0.f);
        }
        xs[k * 32 + r] = v;
    }
    __syncthreads();

    u64 acc[16];
#pragma unroll
    for (int p = 0; p < 16; p++) acc[p] = 0ull;

#pragma unroll 4
    for (int k = 0; k < K; k++) {
        u64 wp = packdup(W[k * HC + col]);
        const u64* xp = xst + k * 16;
#pragma unroll
        for (int p = 0; p < 16; p++) fma2(acc[p], xp[p], wp);
    }

#pragma unroll
    for (int p = 0; p < 16; p++) {
        float2 lh = unpack2(acc[p]);
        int r0 = row0 + 2 * p;
        if (r0 < NN)     Hout[(size_t)r0 * HC + col] = lh.x;
        if (r0 + 1 < NN) Hout[(size_t)(r0 + 1) * HC + col] = lh.y;
    }
}

// ---------------- attention logit vectors ------------------------------------
template <int H, int CH>
__global__ void attn_k(const float* __restrict__ a_src,
                       const float* __restrict__ a_dst) {
    const float* __restrict__ h = (H == NH1) ? g_h1 : g_h2;
    float* als = (H == NH1) ? g_als1 : g_als2;
    float* ald = (H == NH1) ? g_ald1 : g_ald2;

    int idx = blockIdx.x * blockDim.x + threadIdx.x;
    if (idx >= NN * H) return;
    int node = idx / H, hd = idx - node * H;
    const float4* hp = (const float4*)(h + (size_t)node * HC + hd * CH);
    const float4* as4 = (const float4*)(a_src + hd * CH);
    const float4* ad4 = (const float4*)(a_dst + hd * CH);
    float s1 = 0.f, s2 = 0.f;
#pragma unroll
    for (int c = 0; c < CH / 4; c++) {
        float4 v = hp[c], a = as4[c], b = ad4[c];
        s1 = fmaf(v.x, a.x, fmaf(v.y, a.y, fmaf(v.z, a.z, fmaf(v.w, a.w, s1))));
        s2 = fmaf(v.x, b.x, fmaf(v.y, b.y, fmaf(v.z, b.z, fmaf(v.w, b.w, s2))));
    }
    als[idx] = s1;
    ald[idx] = s2;
}

// ---------------- fused GAT layer 1 (16 heads), warp per dst, single pass -----
__global__ void __launch_bounds__(256) gat1_k() {
    int w = (blockIdx.x * blockDim.x + threadIdx.x) >> 5;
    int lane = threadIdx.x & 31;
    if (w >= NN) return;
    const int d = w;
    const int hh = lane & 15;
    const int h0 = lane >> 2, h1 = h0 + 8;

    float ald_h = g_ald1[d * NH1 + hh];
    float wself = __expf(leaky(g_als1[d * NH1 + hh] + ald_h));
    float ssum = wself;

    ulonglong2 acc0, acc1;
    {
        u64 W0 = packdup(__shfl_sync(0xffffffffu, wself, h0));
        u64 W1 = packdup(__shfl_sync(0xffffffffu, wself, h1));
        const ulonglong2* hs = (const ulonglong2*)(g_h1 + (size_t)d * HC);
        ulonglong2 v0 = hs[lane], v1 = hs[lane + 32];
        acc0.x = mul2(v0.x, W0); acc0.y = mul2(v0.y, W0);
        acc1.x = mul2(v1.x, W1); acc1.y = mul2(v1.y, W1);
    }

    int beg = g_rowptr[d], end = g_rowptr[d + 1];

#define GAT1_STEP(SRC)                                                          \
    {                                                                           \
        int s_ = (SRC);                                                         \
        float we = __expf(leaky(g_als1[s_ * NH1 + hh] + ald_h));                \
        ssum += we;                                                             \
        u64 W0 = packdup(__shfl_sync(0xffffffffu, we, h0));                     \
        u64 W1 = packdup(__shfl_sync(0xffffffffu, we, h1));                     \
        const ulonglong2* hs = (const ulonglong2*)(g_h1 + (size_t)s_ * HC);     \
        ulonglong2 v0 = hs[lane], v1 = hs[lane + 32];                           \
        fma2(acc0.x, v0.x, W0); fma2(acc0.y, v0.y, W0);                         \
        fma2(acc1.x, v1.x, W1); fma2(acc1.y, v1.y, W1);                         \
    }

    for (int base = beg; base < end; base += 32) {
        int idx = base + lane;
        int sv = (idx < end) ? g_csr_src[idx] : 0;
        int n = min(32, end - base);
        if (n == 32) {
#pragma unroll 8
            for (int j = 0; j < 32; j++) GAT1_STEP(__shfl_sync(0xffffffffu, sv, j));
        } else {
            for (int j = 0; j < n; j++) GAT1_STEP(__shfl_sync(0xffffffffu, sv, j));
        }
    }

    float s0 = __shfl_sync(0xffffffffu, ssum, h0);
    float s1 = __shfl_sync(0xffffffffu, ssum, h1);
    float r0 = 1.f / s0, r1 = 1.f / s1;
    float2 a0 = unpack2(acc0.x), a1 = unpack2(acc0.y);
    float2 b0 = unpack2(acc1.x), b1 = unpack2(acc1.y);
    float4* od = (float4*)(g_out1 + (size_t)d * HC);
    od[lane]      = make_float4(a0.x * r0, a0.y * r0, a1.x * r0, a1.y * r0);
    od[lane + 32] = make_float4(b0.x * r1, b0.y * r1, b1.x * r1, b1.y * r1);
}

// ---------------- fused GAT layer 2 (1 head) + mean-pool red, single pass -----
__global__ void __launch_bounds__(256) gat2_k(const int* __restrict__ batch) {
    int w = (blockIdx.x * blockDim.x + threadIdx.x) >> 5;
    int lane = threadIdx.x & 31;
    if (w >= NN) return;
    const int d = w;

    float ald_d = g_ald2[d];
    float ssum = __expf(leaky(g_als2[d] + ald_d));

    ulonglong2 acc0, acc1;
    {
        u64 W0 = packdup(ssum);
        const ulonglong2* hs = (const ulonglong2*)(g_h2 + (size_t)d * HC);
        ulonglong2 v0 = hs[lane], v1 = hs[lane + 32];
        acc0.x = mul2(v0.x, W0); acc0.y = mul2(v0.y, W0);
        acc1.x = mul2(v1.x, W0); acc1.y = mul2(v1.y, W0);
    }

    int beg = g_rowptr[d], end = g_rowptr[d + 1];

#define GAT2_STEP(SRC)                                                          \
    {                                                                           \
        int s_ = (SRC);                                                         \
        float we = __expf(leaky(g_als2[s_] + ald_d));                           \
        ssum += we;                                                             \
        u64 W0 = packdup(we);                                                   \
        const ulonglong2* hs = (const ulonglong2*)(g_h2 + (size_t)s_ * HC);     \
        ulonglong2 v0 = hs[lane], v1 = hs[lane + 32];                           \
        fma2(acc0.x, v0.x, W0); fma2(acc0.y, v0.y, W0);                         \
        fma2(acc1.x, v1.x, W0); fma2(acc1.y, v1.y, W0);                         \
    }

    for (int base = beg; base < end; base += 32) {
        int idx = base + lane;
        int sv = (idx < end) ? g_csr_src[idx] : 0;
        int n = min(32, end - base);
        if (n == 32) {
#pragma unroll 8
            for (int j = 0; j < 32; j++) GAT2_STEP(__shfl_sync(0xffffffffu, sv, j));
        } else {
            for (int j = 0; j < n; j++) GAT2_STEP(__shfl_sync(0xffffffffu, sv, j));
        }
    }

    float inv = 1.f / ssum;
    int g = batch[d];
    float2 a0 = unpack2(acc0.x), a1 = unpack2(acc0.y);
    float2 b0 = unpack2(acc1.x), b1 = unpack2(acc1.y);
    redAdd4(&((float4*)(g_sums + g * HC))[lane],
            make_float4(a0.x * inv, a0.y * inv, a1.x * inv, a1.y * inv));
    redAdd4(&((float4*)(g_sums + g * HC))[lane + 32],
            make_float4(b0.x * inv, b0.y * inv, b1.x * inv, b1.y * inv));
    if (lane == 0) atomicAdd(&g_cnts[g], 1.f);
}

// ---------------- final: (mean + b2) @ lin_w + lin_b --------------------------
__global__ void final_k(const float* __restrict__ b2,
                        const float* __restrict__ lw,
                        const float* __restrict__ lb,
                        float* __restrict__ out) {
    __shared__ float p[HC];
    int g = blockIdx.x;
    float cnt = fmaxf(g_cnts[g], 1.f);
    p[threadIdx.x] = g_sums[g * HC + threadIdx.x] / cnt + b2[threadIdx.x];
    __syncthreads();
    if (threadIdx.x < LL) {
        float acc = lb[threadIdx.x];
#pragma unroll 8
        for (int d = 0; d < HC; d++)
            acc = fmaf(p[d], lw[d * LL + threadIdx.x], acc);
        out[g * LL + threadIdx.x] = acc;
    }
}

// ---------------- launch -------------------------------------------------------
extern "C" void kernel_launch(void* const* d_in, const int* in_sizes, int n_in,
                              void* d_out, int out_size) {
    const float* x      = (const float*)d_in[0];
    const int*   ei     = (const int*)d_in[1];
    const int*   batch  = (const int*)d_in[2];
    const float* W1     = (const float*)d_in[3];
    const float* a_src1 = (const float*)d_in[4];
    const float* a_dst1 = (const float*)d_in[5];
    const float* b1     = (const float*)d_in[6];
    const float* W2     = (const float*)d_in[7];
    const float* a_src2 = (const float*)d_in[8];
    const float* a_dst2 = (const float*)d_in[9];
    const float* b2     = (const float*)d_in[10];
    const float* lin_w  = (const float*)d_in[11];
    const float* lin_b  = (const float*)d_in[12];
    float* out = (float*)d_out;

    const int* src = ei;
    const int* dst = ei + EE;

    // one-time host resources (no device memory involved)
    static cudaStream_t s_csr = nullptr;
    static cudaEvent_t ev_init = nullptr, ev_csr = nullptr;
    if (!s_csr) {
        cudaStreamCreateWithFlags(&s_csr, cudaStreamNonBlocking);
        cudaEventCreateWithFlags(&ev_init, cudaEventDisableTiming);
        cudaEventCreateWithFlags(&ev_csr, cudaEventDisableTiming);
    }

    // main stream: init, then fork CSR build onto s_csr
    init_k<<<(GG * HC + 255) / 256, 256>>>();
    cudaEventRecord(ev_init, 0);
    cudaStreamWaitEvent(s_csr, ev_init, 0);
    csr_count<<<(EE / 4 + 255) / 256, 256, 0, s_csr>>>(dst);
    csr_scan<<<1, 1024, 0, s_csr>>>();
    csr_fill<<<(EE / 4 + 255) / 256, 256, 0, s_csr>>>(src, dst);
    cudaEventRecord(ev_csr, s_csr);

    // main stream (concurrent with CSR build): layer-1 GEMM + logits
    gemm_k<1><<<(NN + 31) / 32, 256>>>(x, W1, nullptr);
    attn_k<NH1, NC1><<<(NN * NH1 + 255) / 256, 256>>>(a_src1, a_dst1);

    // join: gat1 needs CSR
    cudaStreamWaitEvent(0, ev_csr, 0);
    gat1_k<<<(NN * 32 + 255) / 256, 256>>>();

    // layer 2 (relu(out1+b1) folded into gemm2 load)
    gemm_k<2><<<(NN + 31) / 32, 256>>>(nullptr, W2, b1);
    attn_k<1, HC><<<(NN + 255) / 256, 256>>>(a_src2, a_dst2);
    gat2_k<<<(NN * 32 + 255) / 256, 256>>>(batch);

    final_k<<<GG, 256>>>(b2, lin_w, lin_b, out);
}

// round 5
// speedup vs baseline: 1.8564x; 1.1227x over previous
#include <cuda_runtime.h>
#include <cuda_fp16.h>
#include <math.h>

#define NN 10000
#define EE 320000
#define FIN 128
#define HC 256
#define NH1 16
#define NC1 16
#define GG 64
#define LL 10

typedef unsigned long long u64;

// ---------------- scratch ----------------------------------------------------
__device__ __half g_h1h[NN * HC];    // layer1 features (fp16 gather copy)
__device__ __half g_h2h[NN * HC];    // layer2 features (fp16 gather copy)
__device__ float g_out1[NN * HC];    // layer1 aggregated output (fp32)
__device__ float g_als1[NN * NH1];
__device__ float g_ald1[NN * NH1];
__device__ float g_als2[NN];
__device__ float g_ald2[NN];
__device__ float g_sums[GG * HC];
__device__ float g_cnts[GG];
__device__ int   g_rowptr[NN + 1];
__device__ int   g_deg[NN];          // histogram -> start-offset cursor
__device__ int   g_csr_src[EE];

__device__ __forceinline__ float leaky(float v) { return v >= 0.f ? v : 0.2f * v; }

__device__ __forceinline__ void redAdd4(float4* addr, float4 v) {
    asm volatile("red.global.add.v4.f32 [%0], {%1, %2, %3, %4};"
                 :: "l"(addr), "f"(v.x), "f"(v.y), "f"(v.z), "f"(v.w) : "memory");
}

__device__ __forceinline__ u64 packdup(float w) {
    u64 r; asm("mov.b64 %0, {%1, %1};" : "=l"(r) : "f"(w)); return r;
}
__device__ __forceinline__ void fma2(u64& acc, u64 x, u64 w) {
    asm("fma.rn.f32x2 %0, %1, %2, %0;" : "+l"(acc) : "l"(x), "l"(w));
}
__device__ __forceinline__ float2 unpack2(u64 v) {
    float lo, hi; asm("mov.b64 {%0, %1}, %2;" : "=f"(lo), "=f"(hi) : "l"(v));
    return make_float2(lo, hi);
}

// ---------------- init kernels -------------------------------------------------
__global__ void zero_deg_k() {
    int i = blockIdx.x * blockDim.x + threadIdx.x;
    if (i < NN) g_deg[i] = 0;
}
__global__ void init_sums_k() {
    int i = blockIdx.x * blockDim.x + threadIdx.x;
    if (i < GG * HC) g_sums[i] = 0.f;
    if (i < GG) g_cnts[i] = 0.f;
}

// ---------------- CSR build ---------------------------------------------------
__global__ void csr_count(const int* __restrict__ dst) {
    int i = blockIdx.x * blockDim.x + threadIdx.x;
    if (i * 4 >= EE) return;
    int4 d4 = ((const int4*)dst)[i];
    atomicAdd(&g_deg[d4.x], 1);
    atomicAdd(&g_deg[d4.y], 1);
    atomicAdd(&g_deg[d4.z], 1);
    atomicAdd(&g_deg[d4.w], 1);
}

__global__ void csr_scan() {                          // 1024 threads, 1 block
    __shared__ int part[1024];
    const int CH = 10;
    int t = threadIdx.x;
    int base = t * CH;
    int s = 0;
#pragma unroll
    for (int j = 0; j < CH; j++) { int idx = base + j; if (idx < NN) s += g_deg[idx]; }
    part[t] = s;
    __syncthreads();
    for (int o = 1; o < 1024; o <<= 1) {
        int v = (t >= o) ? part[t - o] : 0;
        __syncthreads();
        part[t] += v;
        __syncthreads();
    }
    int run = (t == 0) ? 0 : part[t - 1];
#pragma unroll
    for (int j = 0; j < CH; j++) {
        int idx = base + j;
        if (idx < NN) {
            g_rowptr[idx] = run;
            int dg = g_deg[idx];
            g_deg[idx] = run;                         // becomes write cursor
            run += dg;
            if (idx == NN - 1) g_rowptr[NN] = run;
        }
    }
}

__global__ void csr_fill(const int* __restrict__ src, const int* __restrict__ dst) {
    int i = blockIdx.x * blockDim.x + threadIdx.x;
    if (i * 4 >= EE) return;
    int4 s4 = ((const int4*)src)[i];
    int4 d4 = ((const int4*)dst)[i];
    g_csr_src[atomicAdd(&g_deg[d4.x], 1)] = s4.x;
    g_csr_src[atomicAdd(&g_deg[d4.y], 1)] = s4.y;
    g_csr_src[atomicAdd(&g_deg[d4.z], 1)] = s4.z;
    g_csr_src[atomicAdd(&g_deg[d4.w], 1)] = s4.w;
}

// ---------------- GEMM + fused logits + fp16 store ---------------------------
// Hout_half[N,256] = half(X[N,K] @ W[K,256]); als/ald from fp32 accs.
template <int LAYER>
__global__ void __launch_bounds__(256) gemm_k(const float* __restrict__ Xin,
                       const float* __restrict__ W,
                       const float* __restrict__ bin,
                       const float* __restrict__ a_src,
                       const float* __restrict__ a_dst) {
    constexpr int K = (LAYER == 1) ? FIN : HC;
    const float* __restrict__ X = (LAYER == 1) ? Xin : g_out1;
    __half* __restrict__ Hout = (LAYER == 1) ? g_h1h : g_h2h;

    __shared__ u64 xst[K * 16];             // [k][row_pair]
    __shared__ float red[8][64];            // layer-2 logit reduction
    float* xs = (float*)xst;

    int row0 = blockIdx.x * 32;
    int col = threadIdx.x;

    for (int i = threadIdx.x; i < 32 * K; i += 256) {
        int r = i & 31, k = i >> 5;
        int row = row0 + r;
        float v = 0.f;
        if (row < NN) {
            v = X[(size_t)row * K + k];
            if (LAYER == 2) v = fmaxf(v + bin[k], 0.f);
        }
        xs[k * 32 + r] = v;
    }
    __syncthreads();

    u64 acc[16];
#pragma unroll
    for (int p = 0; p < 16; p++) acc[p] = 0ull;

#pragma unroll 4
    for (int k = 0; k < K; k++) {
        u64 wp = packdup(W[k * HC + col]);
        const u64* xp = xst + k * 16;
#pragma unroll
        for (int p = 0; p < 16; p++) fma2(acc[p], xp[p], wp);
    }

    float As = a_src[col], Ad = a_dst[col];

#pragma unroll
    for (int p = 0; p < 16; p++) {
        float2 lh = unpack2(acc[p]);
        int r0 = row0 + 2 * p;
        if (r0 < NN)     Hout[(size_t)r0 * HC + col] = __float2half_rn(lh.x);
        if (r0 + 1 < NN) Hout[(size_t)(r0 + 1) * HC + col] = __float2half_rn(lh.y);

        float vs0 = lh.x * As, vd0 = lh.x * Ad;
        float vs1 = lh.y * As, vd1 = lh.y * Ad;

        if (LAYER == 1) {
            // reduce within 16-lane head groups
#pragma unroll
            for (int o = 1; o < 16; o <<= 1) {
                vs0 += __shfl_xor_sync(0xffffffffu, vs0, o);
                vd0 += __shfl_xor_sync(0xffffffffu, vd0, o);
                vs1 += __shfl_xor_sync(0xffffffffu, vs1, o);
                vd1 += __shfl_xor_sync(0xffffffffu, vd1, o);
            }
            if ((col & 15) == 0) {
                int head = col >> 4;
                if (r0 < NN)     { g_als1[r0 * NH1 + head] = vs0; g_ald1[r0 * NH1 + head] = vd0; }
                if (r0 + 1 < NN) { g_als1[(r0 + 1) * NH1 + head] = vs1; g_ald1[(r0 + 1) * NH1 + head] = vd1; }
            }
        } else {
            // full-block reduction: warp partials -> smem
#pragma unroll
            for (int o = 1; o < 32; o <<= 1) {
                vs0 += __shfl_xor_sync(0xffffffffu, vs0, o);
                vd0 += __shfl_xor_sync(0xffffffffu, vd0, o);
                vs1 += __shfl_xor_sync(0xffffffffu, vs1, o);
                vd1 += __shfl_xor_sync(0xffffffffu, vd1, o);
            }
            if ((col & 31) == 0) {
                int w = col >> 5;
                red[w][p * 4 + 0] = vs0;
                red[w][p * 4 + 1] = vd0;
                red[w][p * 4 + 2] = vs1;
                red[w][p * 4 + 3] = vd1;
            }
        }
    }

    if (LAYER == 2) {
        __syncthreads();
        if (threadIdx.x < 64) {
            int t = threadIdx.x;
            float s = 0.f;
#pragma unroll
            for (int w = 0; w < 8; w++) s += red[w][t];
            int p = t >> 2, q = t & 3;
            int r = row0 + 2 * p + (q >> 1);
            if (r < NN) {
                if ((q & 1) == 0) g_als2[r] = s;
                else              g_ald2[r] = s;
            }
        }
    }
}

// ---------------- fused GAT layer 1 (16 heads), fp16 gather -------------------
__global__ void __launch_bounds__(256) gat1_k() {
    int w = (blockIdx.x * blockDim.x + threadIdx.x) >> 5;
    int lane = threadIdx.x & 31;
    if (w >= NN) return;
    const int d = w;
    const int hh = lane >> 1;            // 8 channels per lane, 16 per head

    float ald_h = g_ald1[d * NH1 + hh];
    float wself = __expf(leaky(g_als1[d * NH1 + hh] + ald_h));
    float ssum = wself;

    float acc[8];
    {
        const uint4* hp = (const uint4*)(g_h1h + (size_t)d * HC) + lane;
        uint4 q = *hp;
        const __half2* h2 = (const __half2*)&q;
#pragma unroll
        for (int k = 0; k < 4; k++) {
            float2 f = __half22float2(h2[k]);
            acc[2 * k] = wself * f.x;
            acc[2 * k + 1] = wself * f.y;
        }
    }

    int beg = g_rowptr[d], end = g_rowptr[d + 1];

#define GAT1_STEP(SRC)                                                          \
    {                                                                           \
        int s_ = (SRC);                                                         \
        float we = __expf(leaky(g_als1[s_ * NH1 + hh] + ald_h));                \
        ssum += we;                                                             \
        uint4 q = *((const uint4*)(g_h1h + (size_t)s_ * HC) + lane);            \
        const __half2* h2 = (const __half2*)&q;                                 \
        _Pragma("unroll")                                                       \
        for (int k = 0; k < 4; k++) {                                           \
            float2 f = __half22float2(h2[k]);                                   \
            acc[2 * k]     = fmaf(we, f.x, acc[2 * k]);                         \
            acc[2 * k + 1] = fmaf(we, f.y, acc[2 * k + 1]);                     \
        }                                                                       \
    }

    for (int base = beg; base < end; base += 32) {
        int idx = base + lane;
        int sv = (idx < end) ? g_csr_src[idx] : 0;
        int n = min(32, end - base);
        if (n == 32) {
#pragma unroll 8
            for (int j = 0; j < 32; j++) GAT1_STEP(__shfl_sync(0xffffffffu, sv, j));
        } else {
            for (int j = 0; j < n; j++) GAT1_STEP(__shfl_sync(0xffffffffu, sv, j));
        }
    }

    float inv = 1.f / ssum;
    float4* od = (float4*)(g_out1 + (size_t)d * HC) + 2 * lane;
    od[0] = make_float4(acc[0] * inv, acc[1] * inv, acc[2] * inv, acc[3] * inv);
    od[1] = make_float4(acc[4] * inv, acc[5] * inv, acc[6] * inv, acc[7] * inv);
}

// ---------------- fused GAT layer 2 (1 head) + mean-pool red ------------------
__global__ void __launch_bounds__(256) gat2_k(const int* __restrict__ batch) {
    int w = (blockIdx.x * blockDim.x + threadIdx.x) >> 5;
    int lane = threadIdx.x & 31;
    if (w >= NN) return;
    const int d = w;

    float ald_d = g_ald2[d];
    float wself = __expf(leaky(g_als2[d] + ald_d));
    float ssum = wself;

    float acc[8];
    {
        uint4 q = *((const uint4*)(g_h2h + (size_t)d * HC) + lane);
        const __half2* h2 = (const __half2*)&q;
#pragma unroll
        for (int k = 0; k < 4; k++) {
            float2 f = __half22float2(h2[k]);
            acc[2 * k] = wself * f.x;
            acc[2 * k + 1] = wself * f.y;
        }
    }

    int beg = g_rowptr[d], end = g_rowptr[d + 1];

#define GAT2_STEP(SRC)                                                          \
    {                                                                           \
        int s_ = (SRC);                                                         \
        float we = __expf(leaky(g_als2[s_] + ald_d));                           \
        ssum += we;                                                             \
        uint4 q = *((const uint4*)(g_h2h + (size_t)s_ * HC) + lane);            \
        const __half2* h2 = (const __half2*)&q;                                 \
        _Pragma("unroll")                                                       \
        for (int k = 0; k < 4; k++) {                                           \
            float2 f = __half22float2(h2[k]);                                   \
            acc[2 * k]     = fmaf(we, f.x, acc[2 * k]);                         \
            acc[2 * k + 1] = fmaf(we, f.y, acc[2 * k + 1]);                     \
        }                                                                       \
    }

    for (int base = beg; base < end; base += 32) {
        int idx = base + lane;
        int sv = (idx < end) ? g_csr_src[idx] : 0;
        int n = min(32, end - base);
        if (n == 32) {
#pragma unroll 8
            for (int j = 0; j < 32; j++) GAT2_STEP(__shfl_sync(0xffffffffu, sv, j));
        } else {
            for (int j = 0; j < n; j++) GAT2_STEP(__shfl_sync(0xffffffffu, sv, j));
        }
    }

    float inv = 1.f / ssum;
    int g = batch[d];
    float4* sd = (float4*)(g_sums + g * HC) + 2 * lane;
    redAdd4(sd,     make_float4(acc[0] * inv, acc[1] * inv, acc[2] * inv, acc[3] * inv));
    redAdd4(sd + 1, make_float4(acc[4] * inv, acc[5] * inv, acc[6] * inv, acc[7] * inv));
    if (lane == 0) atomicAdd(&g_cnts[g], 1.f);
}

// ---------------- final: (mean + b2) @ lin_w + lin_b --------------------------
__global__ void final_k(const float* __restrict__ b2,
                        const float* __restrict__ lw,
                        const float* __restrict__ lb,
                        float* __restrict__ out) {
    __shared__ float p[HC];
    int g = blockIdx.x;
    float cnt = fmaxf(g_cnts[g], 1.f);
    p[threadIdx.x] = g_sums[g * HC + threadIdx.x] / cnt + b2[threadIdx.x];
    __syncthreads();
    if (threadIdx.x < LL) {
        float acc = lb[threadIdx.x];
#pragma unroll 8
        for (int d = 0; d < HC; d++)
            acc = fmaf(p[d], lw[d * LL + threadIdx.x], acc);
        out[g * LL + threadIdx.x] = acc;
    }
}

// ---------------- launch -------------------------------------------------------
extern "C" void kernel_launch(void* const* d_in, const int* in_sizes, int n_in,
                              void* d_out, int out_size) {
    const float* x      = (const float*)d_in[0];
    const int*   ei     = (const int*)d_in[1];
    const int*   batch  = (const int*)d_in[2];
    const float* W1     = (const float*)d_in[3];
    const float* a_src1 = (const float*)d_in[4];
    const float* a_dst1 = (const float*)d_in[5];
    const float* b1     = (const float*)d_in[6];
    const float* W2     = (const float*)d_in[7];
    const float* a_src2 = (const float*)d_in[8];
    const float* a_dst2 = (const float*)d_in[9];
    const float* b2     = (const float*)d_in[10];
    const float* lin_w  = (const float*)d_in[11];
    const float* lin_b  = (const float*)d_in[12];
    float* out = (float*)d_out;

    const int* src = ei;
    const int* dst = ei + EE;

    static cudaStream_t s_csr = nullptr;
    static cudaEvent_t ev_fork = nullptr, ev_csr = nullptr;
    if (!s_csr) {
        cudaStreamCreateWithFlags(&s_csr, cudaStreamNonBlocking);
        cudaEventCreateWithFlags(&ev_fork, cudaEventDisableTiming);
        cudaEventCreateWithFlags(&ev_csr, cudaEventDisableTiming);
    }

    // fork CSR pipeline at graph start
    cudaEventRecord(ev_fork, 0);
    cudaStreamWaitEvent(s_csr, ev_fork, 0);
    zero_deg_k<<<(NN + 255) / 256, 256, 0, s_csr>>>();
    csr_count<<<(EE / 4 + 255) / 256, 256, 0, s_csr>>>(dst);
    csr_scan<<<1, 1024, 0, s_csr>>>();
    csr_fill<<<(EE / 4 + 255) / 256, 256, 0, s_csr>>>(src, dst);
    cudaEventRecord(ev_csr, s_csr);

    // main stream (concurrent): pooled-sum init + layer-1 GEMM (+logits)
    init_sums_k<<<(GG * HC + 255) / 256, 256>>>();
    gemm_k<1><<<(NN + 31) / 32, 256>>>(x, W1, nullptr, a_src1, a_dst1);

    // join: gat1 needs CSR
    cudaStreamWaitEvent(0, ev_csr, 0);
    gat1_k<<<(NN * 32 + 255) / 256, 256>>>();

    // layer 2 (relu(out1+b1) folded into gemm2 load; logits fused)
    gemm_k<2><<<(NN + 31) / 32, 256>>>(nullptr, W2, b1, a_src2, a_dst2);
    gat2_k<<<(NN * 32 + 255) / 256, 256>>>(batch);

    final_k<<<GG, 256>>>(b2, lin_w, lin_b, out);
}